// round 11
// baseline (speedup 1.0000x reference)
#include <cuda_runtime.h>

#define BB 8
#define GG 64
#define PP 32768
#define NC 80
#define NCHUNK 64            // pred chunks per batch (512 preds each)

// per-(batch, chunk) partial argmax keys: (q_bits << 32) | (0xFFFFFFFF - p)
// all scratch fully overwritten every run -> no init needed, graph-safe.
__device__ unsigned long long g_partial[BB * NCHUNK * GG];
__device__ unsigned long long g_final[BB * GG];
__device__ float4 g_rec[BB * PP * 2];   // per-(b,p): {W,Scx,Scy,Slw},{Slh,gth,ign,0}

// Kernel A: one pass over all (g, p) pairs of this block's 512 preds.
// grid = 8*64 = 512 blocks (single wave at 4 CTAs/SM), 256 threads.
// Thread = (gt g = tid&63, r = tid>>6) scanning 128 preds in 4 independent
// argmax sub-chains of 32 (cross-mult compare, FSEL updates, sticky near-tie
// band resolved by exact-division rescan -> ordering == reference rounded-
// quotient argmax). Threshold/ignore candidates pass ONE coarse in-loop
// filter (inter >= 0.39*den, a strict superset of both canonical tests); the
// rare drain re-tests with the canonical forms (0.5f/0.4f), so final th/ign
// decisions are identical to round 10. Also zero-fills this block's cls slice.
__global__ void __launch_bounds__(256) fused_kernel(const float* __restrict__ gt,
                                                    const float* __restrict__ pr,
                                                    float* __restrict__ out) {
    __shared__ float4 s_pc[512];    // px1, px2, py1, py2
    __shared__ float  s_pa[512];
    __shared__ float  s_W[512], s_cx[512], s_cy[512], s_lw[512], s_lh[512];
    __shared__ int    s_gth[512], s_ign[512];
    __shared__ unsigned long long s_key[256];

    int tid = threadIdx.x;
    int b = blockIdx.x >> 6;
    int chunk = blockIdx.x & (NCHUNK - 1);
    int pbase = chunk * 512;

#pragma unroll
    for (int j = 0; j < 2; j++) {   // stage 512 preds
        int p = j * 256 + tid;
        float4 v = ((const float4*)pr)[pbase + p];   // pr_boxes[0] per reference
        s_pc[p] = make_float4(v.x - v.z * 0.5f, v.x + v.z * 0.5f,
                              v.y - v.w * 0.5f, v.y + v.w * 0.5f);
        s_pa[p] = v.z * v.w;
        s_W[p] = 0.f; s_cx[p] = 0.f; s_cy[p] = 0.f;
        s_lw[p] = 0.f; s_lh[p] = 0.f;
        s_gth[p] = -1; s_ign[p] = 0;
    }

    {   // zero-fill this block's cls slice; stores drain under compute
        float4* zc = (float4*)out + (size_t)blockIdx.x * 10240;
        float4 z = make_float4(0.f, 0.f, 0.f, 0.f);
#pragma unroll
        for (int i = 0; i < 40; i++) zc[i * 256 + tid] = z;
    }

    int g = tid & 63, r = tid >> 6;
    const float* grow = gt + (b * GG + g) * 6;
    float cx = grow[0], cy = grow[1], gw = grow[2], gh = grow[3];
    bool valid = (cx != -1.0f);
    float gx1 = cx - gw * 0.5f, gx2 = cx + gw * 0.5f;
    float gy1 = cy - gh * 0.5f, gy2 = cy + gh * 0.5f;
    float gaeps = gw * gh + 1e-5f;
    // invalid gt (cx=-1): inverted corners -> iw/ih clamp to 0, inter=0,
    // den>0, so events stay false and the argmax key is gated by 'valid'.
    __syncthreads();

    int base = r * 128;
    // 4 independent sub-chains over preds base+[0,32), [32,64), [64,96), [96,128)
    float bn0 = 0.f, bd0 = 1.f; int bp0 = base;
    float bn1 = 0.f, bd1 = 1.f; int bp1 = base + 32;
    float bn2 = 0.f, bd2 = 1.f; int bp2 = base + 64;
    float bn3 = 0.f, bd3 = 1.f; int bp3 = base + 96;
    unsigned m0 = 0, m1 = 0, m2 = 0, m3 = 0;
    bool band = false;

#pragma unroll 4
    for (int i = 0; i < 32; i++) {
        unsigned bit = 1u << i;
        {   // chain 0
            float4 c = s_pc[base + i];
            float pa = s_pa[base + i];
            float iw = fmaxf(0.f, fminf(gx2, c.y) - fmaxf(gx1, c.x));
            float ih = fmaxf(0.f, fminf(gy2, c.w) - fmaxf(gy1, c.z));
            float inter = iw * ih;
            float den = (gaeps + pa) - inter;
            float a = inter * bd0, cc = bn0 * den;
            bool acc = a > cc;
            float d = a - cc;
            band = band || ((d != 0.f) && (fabsf(d) <= cc * 1e-6f));
            bn0 = acc ? inter : bn0;
            bd0 = acc ? den : bd0;
            bp0 = acc ? base + i : bp0;
            m0 |= (inter >= 0.39f * den) ? bit : 0u;
        }
        {   // chain 1
            float4 c = s_pc[base + 32 + i];
            float pa = s_pa[base + 32 + i];
            float iw = fmaxf(0.f, fminf(gx2, c.y) - fmaxf(gx1, c.x));
            float ih = fmaxf(0.f, fminf(gy2, c.w) - fmaxf(gy1, c.z));
            float inter = iw * ih;
            float den = (gaeps + pa) - inter;
            float a = inter * bd1, cc = bn1 * den;
            bool acc = a > cc;
            float d = a - cc;
            band = band || ((d != 0.f) && (fabsf(d) <= cc * 1e-6f));
            bn1 = acc ? inter : bn1;
            bd1 = acc ? den : bd1;
            bp1 = acc ? base + 32 + i : bp1;
            m1 |= (inter >= 0.39f * den) ? bit : 0u;
        }
        {   // chain 2
            float4 c = s_pc[base + 64 + i];
            float pa = s_pa[base + 64 + i];
            float iw = fmaxf(0.f, fminf(gx2, c.y) - fmaxf(gx1, c.x));
            float ih = fmaxf(0.f, fminf(gy2, c.w) - fmaxf(gy1, c.z));
            float inter = iw * ih;
            float den = (gaeps + pa) - inter;
            float a = inter * bd2, cc = bn2 * den;
            bool acc = a > cc;
            float d = a - cc;
            band = band || ((d != 0.f) && (fabsf(d) <= cc * 1e-6f));
            bn2 = acc ? inter : bn2;
            bd2 = acc ? den : bd2;
            bp2 = acc ? base + 64 + i : bp2;
            m2 |= (inter >= 0.39f * den) ? bit : 0u;
        }
        {   // chain 3
            float4 c = s_pc[base + 96 + i];
            float pa = s_pa[base + 96 + i];
            float iw = fmaxf(0.f, fminf(gx2, c.y) - fmaxf(gx1, c.x));
            float ih = fmaxf(0.f, fminf(gy2, c.w) - fmaxf(gy1, c.z));
            float inter = iw * ih;
            float den = (gaeps + pa) - inter;
            float a = inter * bd3, cc = bn3 * den;
            bool acc = a > cc;
            float d = a - cc;
            band = band || ((d != 0.f) && (fabsf(d) <= cc * 1e-6f));
            bn3 = acc ? inter : bn3;
            bd3 = acc ? den : bd3;
            bp3 = acc ? base + 96 + i : bp3;
            m3 |= (inter >= 0.39f * den) ? bit : 0u;
        }
    }
    {   // merge tree; lower-index chain wins ties (strict > everywhere)
        float a, cc; bool acc; float d;
        a = bn1 * bd0; cc = bn0 * bd1;
        acc = a > cc; d = a - cc;
        band = band || ((d != 0.f) && (fabsf(d) <= cc * 1e-6f));
        if (acc) { bn0 = bn1; bd0 = bd1; bp0 = bp1; }
        a = bn3 * bd2; cc = bn2 * bd3;
        acc = a > cc; d = a - cc;
        band = band || ((d != 0.f) && (fabsf(d) <= cc * 1e-6f));
        if (acc) { bn2 = bn3; bd2 = bd3; bp2 = bp3; }
        a = bn2 * bd0; cc = bn0 * bd2;
        acc = a > cc; d = a - cc;
        band = band || ((d != 0.f) && (fabsf(d) <= cc * 1e-6f));
        if (acc) { bn0 = bn2; bd0 = bd2; bp0 = bp2; }
    }
    // near-tie fallback: exact rounded-quotient rescan (essentially never taken)
    if (__any_sync(0xFFFFFFFFu, band)) {
        if (band) {
            float bq = 0.f; int bpx = base;
            for (int i = 0; i < 128; i++) {
                float4 c = s_pc[base + i];
                float pa = s_pa[base + i];
                float iw = fmaxf(0.f, fminf(gx2, c.y) - fmaxf(gx1, c.x));
                float ih = fmaxf(0.f, fminf(gy2, c.w) - fmaxf(gy1, c.z));
                float inter = iw * ih;
                float den = (gaeps + pa) - inter;
                float qq = inter / den;
                if (qq > bq) { bq = qq; bpx = base + i; }
            }
            bn0 = bq; bd0 = 1.f; bp0 = bpx;
        }
    }
    float q = bn0 / bd0;               // one exact div -> reference-rounded key
    s_key[tid] = valid
        ? (((unsigned long long)__float_as_uint(q) << 32) |
           (unsigned)(0xFFFFFFFFu - (unsigned)(pbase + bp0)))
        : 0ULL;

    // drain rare candidate events; re-test with the canonical threshold forms
    unsigned long long evA = ((unsigned long long)m1 << 32) | m0;   // preds base..base+63
    unsigned long long evB = ((unsigned long long)m3 << 32) | m2;   // preds base+64..base+127
    if (!valid) { evA = 0ULL; evB = 0ULL; }
    if (evA | evB) {
        float lw = logf(gw), lh = logf(gh);
#pragma unroll
        for (int half = 0; half < 2; half++) {
            unsigned long long evm = half ? evB : evA;
            int hbase = base + half * 64;
            while (evm) {
                int i = __ffsll(evm) - 1; evm &= evm - 1;
                int pp = hbase + i;
                float4 c = s_pc[pp];
                float pa = s_pa[pp];
                float iw = fmaxf(0.f, fminf(gx2, c.y) - fmaxf(gx1, c.x));
                float ih = fmaxf(0.f, fminf(gy2, c.w) - fmaxf(gy1, c.z));
                float inter = iw * ih;
                float den = (gaeps + pa) - inter;
                if (inter >= 0.5f * den) {              // th (canonical form)
                    atomicAdd(&s_W[pp], 1.f);
                    atomicAdd(&s_cx[pp], cx);
                    atomicAdd(&s_cy[pp], cy);
                    atomicAdd(&s_lw[pp], lw);
                    atomicAdd(&s_lh[pp], lh);
                    atomicMax(&s_gth[pp], g);
                } else if (inter >= 0.4f * den) {       // ignore band (canonical)
                    s_ign[pp] = 1;                      // benign race: all store 1
                }
            }
        }
    }
    __syncthreads();

    if (tid < GG) {                     // per-(block, gt) argmax partial
        unsigned long long k0 = s_key[tid],       k1 = s_key[tid + 64];
        unsigned long long k2 = s_key[tid + 128], k3 = s_key[tid + 192];
        unsigned long long k = k0 > k1 ? k0 : k1;
        unsigned long long m = k2 > k3 ? k2 : k3;
        k = k > m ? k : m;
        g_partial[(size_t)blockIdx.x * GG + tid] = k;
    }

#pragma unroll
    for (int j = 0; j < 2; j++) {       // per-pred records (2 per thread)
        int p = j * 256 + tid;
        size_t idx = (size_t)b * PP + pbase + p;
        g_rec[idx * 2]     = make_float4(s_W[p], s_cx[p], s_cy[p], s_lw[p]);
        g_rec[idx * 2 + 1] = make_float4(s_lh[p], __int_as_float(s_gth[p]),
                                         __int_as_float(s_ign[p]), 0.f);
    }
}

// Kernel A2: reduce 64 chunk-partials -> one key per (b, g). grid 8 x 256.
__global__ void reduce_kernel() {
    __shared__ unsigned long long s_red[256];
    int tid = threadIdx.x;
    int b = blockIdx.x;
    int g = tid & 63, qd = tid >> 6;
    unsigned long long k = 0ULL;
    const unsigned long long* src = g_partial + ((size_t)b * NCHUNK + qd * 16) * GG + g;
#pragma unroll
    for (int i = 0; i < 16; i++) {
        unsigned long long v = src[(size_t)i * GG];
        k = v > k ? v : k;
    }
    s_red[tid] = k;
    __syncthreads();
    if (tid < GG) {
        unsigned long long k0 = s_red[tid],       k1 = s_red[tid + 64];
        unsigned long long k2 = s_red[tid + 128], k3 = s_red[tid + 192];
        unsigned long long a = k0 > k1 ? k0 : k1;
        unsigned long long c = k2 > k3 ? k2 : k3;
        g_final[b * GG + tid] = a > c ? a : c;
    }
}

// Kernel B: merge best-pair term + finalize. No per-gt loop. grid (128, 8).
__global__ void __launch_bounds__(256) finalize_kernel(const float* __restrict__ gt,
                                                       const float* __restrict__ pr,
                                                       float* __restrict__ out) {
    __shared__ float s_bw[256], s_bx[256], s_by[256], s_blw[256], s_blh[256];
    __shared__ int   s_bg[256];
    __shared__ float s_lab[GG];

    int tid = threadIdx.x;
    int b = blockIdx.y;

    s_bw[tid] = 0.f; s_bx[tid] = 0.f; s_by[tid] = 0.f;
    s_blw[tid] = 0.f; s_blh[tid] = 0.f; s_bg[tid] = -1;

    if (tid < GG) {
        const float* grow = gt + (b * GG + tid) * 6;
        float cx = grow[0];
        s_lab[tid] = grow[4];
        bool valid = (cx != -1.0f);
        float conf = grow[5];
        if (valid && conf > 0.f) {
            unsigned long long k = g_final[b * GG + tid];
            int bp = (int)(0xFFFFFFFFu - (unsigned)(k & 0xFFFFFFFFull));
            if ((bp >> 8) == (int)blockIdx.x) {     // best pred lives in this block
                int lp = bp & 255;
                atomicAdd(&s_bw[lp], 1.f);
                atomicAdd(&s_bx[lp], cx);
                atomicAdd(&s_by[lp], grow[1]);
                atomicAdd(&s_blw[lp], logf(grow[2]));
                atomicAdd(&s_blh[lp], logf(grow[3]));
                atomicMax(&s_bg[lp], tid);          // original gt index (monotone)
            }
        }
    }
    __syncthreads();

    int p = blockIdx.x * 256 + tid;
    size_t idx = (size_t)b * PP + p;
    float4 r0 = g_rec[idx * 2];
    float4 r1 = g_rec[idx * 2 + 1];

    float W   = r0.x + s_bw[tid];
    float Scx = r0.y + s_bx[tid];
    float Scy = r0.z + s_by[tid];
    float Slw = r0.w + s_blw[tid];
    float Slh = r1.x + s_blh[tid];
    int gth = __float_as_int(r1.y);
    bool ign = __float_as_int(r1.z) != 0;
    int gbe = s_bg[tid];

    int win = (gbe >= 0) ? gbe : gth;
    bool matched = (win >= 0);
    float mask = matched ? 0.f : 1.f;
    if (ign) mask = -1.f;

    float4 pv = ((const float4*)pr)[p];
    float4 loc;
    if (W > 0.f) {
        loc = make_float4((Scx - W * pv.x) / pv.z,
                          (Scy - W * pv.y) / pv.w,
                          Slw - W * logf(pv.z),
                          Slh - W * logf(pv.w));
    } else {
        loc = make_float4(0.f, 0.f, 0.f, 0.f);      // exact: sums are 0 when W==0
    }

    float* out_loc  = out + (size_t)BB * PP * NC;
    float* out_mask = out + (size_t)BB * PP * (NC + 4);
    ((float4*)out_loc)[idx] = loc;
    out_mask[idx] = mask;

    if (matched) {                                  // sparse one-hot scatter
        int cid = (int)s_lab[win];
        out[idx * NC + cid] = 1.0f;
    }
}

extern "C" void kernel_launch(void* const* d_in, const int* in_sizes, int n_in,
                              void* d_out, int out_size) {
    const float* gt = (const float*)d_in[0];   // [8,64,6]
    const float* pr = (const float*)d_in[1];   // [8,32768,4]
    float* out = (float*)d_out;                // cls ++ loc ++ mask

    fused_kernel<<<BB * NCHUNK, 256>>>(gt, pr, out);
    reduce_kernel<<<BB, 256>>>();
    dim3 gridB(PP / 256, BB);
    finalize_kernel<<<gridB, 256>>>(gt, pr, out);
}

// round 12
// speedup vs baseline: 1.1030x; 1.1030x over previous
#include <cuda_runtime.h>

#define BB 8
#define GG 64
#define PP 32768
#define NC 80
#define NCHUNK 128           // pred chunks per batch (256 preds each)
#define NTHR 192             // 4 replicas x 48 compacted queries

// per-(batch, chunk) partial argmax keys: (q_bits << 32) | (0xFFFFFFFF - p)
// all scratch fully overwritten every run -> no init needed, graph-safe.
__device__ unsigned long long g_partial[BB * NCHUNK * GG];
__device__ unsigned long long g_final[BB * GG];
__device__ float4 g_rec[BB * PP * 2];   // per-(b,p): {W,Scx,Scy,Slw},{Slh,gth,ign,0}

// Kernel A: one pass over all (valid-gt, p) pairs of this block's 256 preds.
// Valid gts are ballot-compacted (48 of 64) so no pair work is spent on
// invalid gts. Thread = (query q = tid%48, replica r = tid/48); each thread
// scans 64 preds in 2 independent argmax sub-chains (cross-mult compare,
// FSEL updates, sticky 1e-6 near-tie band resolved by exact-division rescan
// -> ordering == reference rounded-quotient argmax). Threshold/ignore
// candidates pass ONE coarse in-loop filter (inter >= 0.39*den); the rare
// drain re-tests with canonical forms (0.5f/0.4f) -> decisions identical to
// round 10. Also zero-fills this block's cls slice.
__global__ void __launch_bounds__(NTHR, 7) fused_kernel(const float* __restrict__ gt,
                                                        const float* __restrict__ pr,
                                                        float* __restrict__ out) {
    __shared__ float4 s_pc[256];    // px1, px2, py1, py2
    __shared__ float  s_pa[256];
    __shared__ float  s_W[256], s_cx[256], s_cy[256], s_lw[256], s_lh[256];
    __shared__ int    s_gth[256], s_ign[256];
    __shared__ unsigned long long s_key[256];   // [replica][gt-original]
    __shared__ float4 s_gbox[GG];   // gx1, gx2, gy1, gy2 (compacted)
    __shared__ float4 s_gm[GG];     // cx, cy, gw, gh     (compacted)
    __shared__ float  s_gS[GG];     // ga + 1e-5          (compacted)
    __shared__ int    s_gid[GG];    // compacted -> original g
    __shared__ int    s_cnt[2];
    __shared__ int    s_ng;

    int tid = threadIdx.x;
    int b = blockIdx.x >> 7;
    int chunk = blockIdx.x & (NCHUNK - 1);
    int pbase = chunk * 256;

    // stage preds + zero accumulators + zero keys
    for (int p = tid; p < 256; p += NTHR) {
        float4 v = ((const float4*)pr)[pbase + p];   // pr_boxes[0] per reference
        s_pc[p] = make_float4(v.x - v.z * 0.5f, v.x + v.z * 0.5f,
                              v.y - v.w * 0.5f, v.y + v.w * 0.5f);
        s_pa[p] = v.z * v.w;
        s_W[p] = 0.f; s_cx[p] = 0.f; s_cy[p] = 0.f;
        s_lw[p] = 0.f; s_lh[p] = 0.f;
        s_gth[p] = -1; s_ign[p] = 0;
        s_key[p] = 0ULL;
    }

    {   // zero-fill this block's cls slice; stores drain under compute
        float4* zc = (float4*)out + (size_t)blockIdx.x * 5120;
        float4 z = make_float4(0.f, 0.f, 0.f, 0.f);
        for (int i = tid; i < 5120; i += NTHR) zc[i] = z;
    }

    // ballot-compact valid gts (threads 0..63 = warps 0,1 fully active)
    float cx = 0.f, cy = 0.f, gw = 0.f, gh = 0.f;
    bool valid = false;
    int off = 0;
    if (tid < GG) {
        const float* grow = gt + (b * GG + tid) * 6;
        cx = grow[0]; cy = grow[1]; gw = grow[2]; gh = grow[3];
        valid = (cx != -1.0f);
        unsigned m = __ballot_sync(0xFFFFFFFFu, valid);
        off = __popc(m & ((1u << (tid & 31)) - 1));
        if ((tid & 31) == 0) s_cnt[tid >> 5] = __popc(m);
    }
    __syncthreads();
    if (tid < GG) {
        if (tid == 0) s_ng = s_cnt[0] + s_cnt[1];
        if (valid) {
            int d = ((tid < 32) ? 0 : s_cnt[0]) + off;
            s_gbox[d] = make_float4(cx - gw * 0.5f, cx + gw * 0.5f,
                                    cy - gh * 0.5f, cy + gh * 0.5f);
            s_gm[d] = make_float4(cx, cy, gw, gh);
            s_gS[d] = gw * gh + 1e-5f;
            s_gid[d] = tid;
        }
    }
    __syncthreads();
    int ng = s_ng;

    int r = tid / 48, q0 = tid % 48;
    int base = r * 64;

    for (int q = q0; q < ng; q += 48) {     // 1 iteration when ng <= 48
        int g = s_gid[q];
        float4 gb = s_gbox[q];
        float gaeps = s_gS[q];
        float gx1 = gb.x, gx2 = gb.y, gy1 = gb.z, gy2 = gb.w;

        float bn0 = 0.f, bd0 = 1.f; int bp0 = base;        // chain 0: base+0..31
        float bn1 = 0.f, bd1 = 1.f; int bp1 = base + 32;   // chain 1: base+32..63
        unsigned m0 = 0, m1 = 0;
        bool band = false;

#pragma unroll 8
        for (int i = 0; i < 32; i++) {
            unsigned bit = 1u << i;
            {   // chain 0
                float4 c = s_pc[base + i];
                float pa = s_pa[base + i];
                float iw = fmaxf(0.f, fminf(gx2, c.y) - fmaxf(gx1, c.x));
                float ih = fmaxf(0.f, fminf(gy2, c.w) - fmaxf(gy1, c.z));
                float inter = iw * ih;
                float den = (gaeps + pa) - inter;
                float a = inter * bd0, cc = bn0 * den;
                bool acc = a > cc;
                float d = a - cc;
                band = band || ((d != 0.f) && (fabsf(d) <= cc * 1e-6f));
                bn0 = acc ? inter : bn0;
                bd0 = acc ? den : bd0;
                bp0 = acc ? base + i : bp0;
                m0 |= (inter >= 0.39f * den) ? bit : 0u;   // coarse event filter
            }
            {   // chain 1
                float4 c = s_pc[base + 32 + i];
                float pa = s_pa[base + 32 + i];
                float iw = fmaxf(0.f, fminf(gx2, c.y) - fmaxf(gx1, c.x));
                float ih = fmaxf(0.f, fminf(gy2, c.w) - fmaxf(gy1, c.z));
                float inter = iw * ih;
                float den = (gaeps + pa) - inter;
                float a = inter * bd1, cc = bn1 * den;
                bool acc = a > cc;
                float d = a - cc;
                band = band || ((d != 0.f) && (fabsf(d) <= cc * 1e-6f));
                bn1 = acc ? inter : bn1;
                bd1 = acc ? den : bd1;
                bp1 = acc ? base + 32 + i : bp1;
                m1 |= (inter >= 0.39f * den) ? bit : 0u;   // coarse event filter
            }
        }
        {   // merge chains (chain 0 holds lower indices -> keep on tie)
            float a = bn1 * bd0, cc = bn0 * bd1;
            bool acc = a > cc;
            float d = a - cc;
            band = band || ((d != 0.f) && (fabsf(d) <= cc * 1e-6f));
            if (acc) { bn0 = bn1; bd0 = bd1; bp0 = bp1; }
        }
        // near-tie fallback: exact rounded-quotient rescan (essentially never)
        if (band) {
            float bq = 0.f; int bpx = base;
            for (int i = 0; i < 64; i++) {
                float4 c = s_pc[base + i];
                float pa = s_pa[base + i];
                float iw = fmaxf(0.f, fminf(gx2, c.y) - fmaxf(gx1, c.x));
                float ih = fmaxf(0.f, fminf(gy2, c.w) - fmaxf(gy1, c.z));
                float inter = iw * ih;
                float den = (gaeps + pa) - inter;
                float qq = inter / den;
                if (qq > bq) { bq = qq; bpx = base + i; }
            }
            bn0 = bq; bd0 = 1.f; bp0 = bpx;
        }
        float qv = bn0 / bd0;          // one exact div -> reference-rounded key
        s_key[r * GG + g] =
            (((unsigned long long)__float_as_uint(qv) << 32) |
             (unsigned)(0xFFFFFFFFu - (unsigned)(pbase + bp0)));

        // drain rare candidate events; re-test with canonical threshold forms
        unsigned long long evm = ((unsigned long long)m1 << 32) | m0;
        if (evm) {
            float4 gm = s_gm[q];
            float lw = logf(gm.z), lh = logf(gm.w);
            do {
                int i = __ffsll(evm) - 1; evm &= evm - 1;
                int pp = base + i;
                float4 c = s_pc[pp];
                float pa = s_pa[pp];
                float iw = fmaxf(0.f, fminf(gx2, c.y) - fmaxf(gx1, c.x));
                float ih = fmaxf(0.f, fminf(gy2, c.w) - fmaxf(gy1, c.z));
                float inter = iw * ih;
                float den = (gaeps + pa) - inter;
                if (inter >= 0.5f * den) {              // th (canonical form)
                    atomicAdd(&s_W[pp], 1.f);
                    atomicAdd(&s_cx[pp], gm.x);
                    atomicAdd(&s_cy[pp], gm.y);
                    atomicAdd(&s_lw[pp], lw);
                    atomicAdd(&s_lh[pp], lh);
                    atomicMax(&s_gth[pp], g);           // original gt index
                } else if (inter >= 0.4f * den) {       // ignore band (canonical)
                    s_ign[pp] = 1;                      // benign race: all store 1
                }
            } while (evm);
        }
    }
    __syncthreads();

    if (tid < GG) {                     // per-(block, gt) argmax partial
        unsigned long long k0 = s_key[tid],       k1 = s_key[tid + 64];
        unsigned long long k2 = s_key[tid + 128], k3 = s_key[tid + 192];
        unsigned long long k = k0 > k1 ? k0 : k1;
        unsigned long long m = k2 > k3 ? k2 : k3;
        k = k > m ? k : m;
        g_partial[(size_t)blockIdx.x * GG + tid] = k;
    }

    for (int p = tid; p < 256; p += NTHR) {   // per-pred records
        size_t idx = (size_t)b * PP + pbase + p;
        g_rec[idx * 2]     = make_float4(s_W[p], s_cx[p], s_cy[p], s_lw[p]);
        g_rec[idx * 2 + 1] = make_float4(s_lh[p], __int_as_float(s_gth[p]),
                                         __int_as_float(s_ign[p]), 0.f);
    }
}

// Kernel A2: reduce 128 chunk-partials -> one key per (b, g). grid 8 x 256.
__global__ void reduce_kernel() {
    __shared__ unsigned long long s_red[256];
    int tid = threadIdx.x;
    int b = blockIdx.x;
    int g = tid & 63, qd = tid >> 6;
    unsigned long long k = 0ULL;
    const unsigned long long* src = g_partial + ((size_t)b * NCHUNK + qd * 32) * GG + g;
#pragma unroll
    for (int i = 0; i < 32; i++) {
        unsigned long long v = src[(size_t)i * GG];
        k = v > k ? v : k;
    }
    s_red[tid] = k;
    __syncthreads();
    if (tid < GG) {
        unsigned long long k0 = s_red[tid],       k1 = s_red[tid + 64];
        unsigned long long k2 = s_red[tid + 128], k3 = s_red[tid + 192];
        unsigned long long a = k0 > k1 ? k0 : k1;
        unsigned long long c = k2 > k3 ? k2 : k3;
        g_final[b * GG + tid] = a > c ? a : c;
    }
}

// Kernel B: merge best-pair term + finalize. No per-gt loop. grid (128, 8).
__global__ void __launch_bounds__(256) finalize_kernel(const float* __restrict__ gt,
                                                       const float* __restrict__ pr,
                                                       float* __restrict__ out) {
    __shared__ float s_bw[256], s_bx[256], s_by[256], s_blw[256], s_blh[256];
    __shared__ int   s_bg[256];
    __shared__ float s_lab[GG];

    int tid = threadIdx.x;
    int b = blockIdx.y;

    s_bw[tid] = 0.f; s_bx[tid] = 0.f; s_by[tid] = 0.f;
    s_blw[tid] = 0.f; s_blh[tid] = 0.f; s_bg[tid] = -1;

    if (tid < GG) {
        const float* grow = gt + (b * GG + tid) * 6;
        float cx = grow[0];
        s_lab[tid] = grow[4];
        bool valid = (cx != -1.0f);
        float conf = grow[5];
        if (valid && conf > 0.f) {
            unsigned long long k = g_final[b * GG + tid];
            int bp = (int)(0xFFFFFFFFu - (unsigned)(k & 0xFFFFFFFFull));
            if ((bp >> 8) == (int)blockIdx.x) {     // best pred lives in this block
                int lp = bp & 255;
                atomicAdd(&s_bw[lp], 1.f);
                atomicAdd(&s_bx[lp], cx);
                atomicAdd(&s_by[lp], grow[1]);
                atomicAdd(&s_blw[lp], logf(grow[2]));
                atomicAdd(&s_blh[lp], logf(grow[3]));
                atomicMax(&s_bg[lp], tid);          // original gt index (monotone)
            }
        }
    }
    __syncthreads();

    int p = blockIdx.x * 256 + tid;
    size_t idx = (size_t)b * PP + p;
    float4 r0 = g_rec[idx * 2];
    float4 r1 = g_rec[idx * 2 + 1];

    float W   = r0.x + s_bw[tid];
    float Scx = r0.y + s_bx[tid];
    float Scy = r0.z + s_by[tid];
    float Slw = r0.w + s_blw[tid];
    float Slh = r1.x + s_blh[tid];
    int gth = __float_as_int(r1.y);
    bool ign = __float_as_int(r1.z) != 0;
    int gbe = s_bg[tid];

    int win = (gbe >= 0) ? gbe : gth;
    bool matched = (win >= 0);
    float mask = matched ? 0.f : 1.f;
    if (ign) mask = -1.f;

    float4 pv = ((const float4*)pr)[p];
    float4 loc;
    if (W > 0.f) {
        loc = make_float4((Scx - W * pv.x) / pv.z,
                          (Scy - W * pv.y) / pv.w,
                          Slw - W * logf(pv.z),
                          Slh - W * logf(pv.w));
    } else {
        loc = make_float4(0.f, 0.f, 0.f, 0.f);      // exact: sums are 0 when W==0
    }

    float* out_loc  = out + (size_t)BB * PP * NC;
    float* out_mask = out + (size_t)BB * PP * (NC + 4);
    ((float4*)out_loc)[idx] = loc;
    out_mask[idx] = mask;

    if (matched) {                                  // sparse one-hot scatter
        int cid = (int)s_lab[win];
        out[idx * NC + cid] = 1.0f;
    }
}

extern "C" void kernel_launch(void* const* d_in, const int* in_sizes, int n_in,
                              void* d_out, int out_size) {
    const float* gt = (const float*)d_in[0];   // [8,64,6]
    const float* pr = (const float*)d_in[1];   // [8,32768,4]
    float* out = (float*)d_out;                // cls ++ loc ++ mask

    fused_kernel<<<BB * NCHUNK, NTHR>>>(gt, pr, out);
    reduce_kernel<<<BB, 256>>>();
    dim3 gridB(PP / 256, BB);
    finalize_kernel<<<gridB, 256>>>(gt, pr, out);
}